// round 2
// baseline (speedup 1.0000x reference)
#include <cuda_runtime.h>
#include <cstdint>

#define N_GRAPH   4096
#define NPG       32
#define N_NODES   (N_GRAPH * NPG)      // 131072
#define N_EDGES   (N_NODES * 16)       // 2097152
#define INV_SQRT3 0.57735026918962576451f
#define INV_SQRT2 0.70710678118654752440f

// ---------------- scratch (static device arrays) -----------------------------
__device__ int   g_cnt[N_NODES];
__device__ int   g_off[N_NODES + 1];
__device__ int   g_cur[N_NODES];
__device__ int   g_bs [256];
__device__ int   g_src[N_EDGES];
__device__ __align__(16) float4 g_geo[N_EDGES];       // ux,uy,uz,dist (sorted by receiver)

__device__ __align__(16) float g_x0b[N_NODES * 4];
__device__ __align__(16) float g_x1b[N_NODES * 12];
__device__ __align__(16) float g_x0c[N_NODES * 4];
__device__ __align__(16) float g_x1c[N_NODES * 12];
__device__ __align__(16) float g_f  [N_NODES * 4];

// ---------------- helpers ---------------------------------------------------
__device__ __forceinline__ float sigmoidf(float x) {
    return 1.0f / (1.0f + __expf(-x));
}

__device__ __forceinline__ void rbf_from_dist(float dist, float rbf[8]) {
#pragma unroll
    for (int b = 0; b < 8; b++) {
        float t = dist - 0.5f * (float)b;          // centers = linspace(0,3.5,8)
        rbf[b] = __expf(-4.0f * t * t);
    }
}

// one radial path: R[4] = relu(rbf @ w1[p] + b1[p]) @ w2[p] + b2[p]
__device__ __forceinline__ void radial(int p, const float rbf[8], float R[4],
                                       const float* sw1, const float* sb1,
                                       const float* sw2, const float* sb2) {
    float h[8];
    const float* w1 = sw1 + p * 64;
#pragma unroll
    for (int j = 0; j < 8; j++) h[j] = sb1[p*8 + j];
#pragma unroll
    for (int b = 0; b < 8; b++) {
        float rb = rbf[b];
#pragma unroll
        for (int j = 0; j < 8; j++) h[j] = fmaf(rb, w1[b*8 + j], h[j]);
    }
#pragma unroll
    for (int j = 0; j < 8; j++) h[j] = fmaxf(h[j], 0.0f);
    const float* w2 = sw2 + p * 32;
#pragma unroll
    for (int c = 0; c < 4; c++) R[c] = sb2[p*4 + c];
#pragma unroll
    for (int j = 0; j < 8; j++) {
        float hj = h[j];
#pragma unroll
        for (int c = 0; c < 4; c++) R[c] = fmaf(hj, w2[j*4 + c], R[c]);
    }
}

#define LOAD_RADIAL_SMEM(rw1, rb1, rw2, rb2)                                   \
    __shared__ float sw1[576], sb1[72], sw2[288], sb2[36];                     \
    for (int i = threadIdx.x; i < 576; i += blockDim.x) sw1[i] = rw1[i];       \
    for (int i = threadIdx.x; i < 72;  i += blockDim.x) sb1[i] = rb1[i];       \
    for (int i = threadIdx.x; i < 288; i += blockDim.x) sw2[i] = rw2[i];       \
    for (int i = threadIdx.x; i < 36;  i += blockDim.x) sb2[i] = rb2[i];

// ---------------- CSR build --------------------------------------------------
__global__ void k_zero() {
    int i = blockIdx.x * blockDim.x + threadIdx.x;   // 32768 int4
    if (i < N_NODES / 4) ((int4*)g_cnt)[i] = make_int4(0, 0, 0, 0);
}

__global__ void k_hist(const int* __restrict__ rcv) {
    int e = blockIdx.x * blockDim.x + threadIdx.x;
    if (e < N_EDGES) atomicAdd(&g_cnt[rcv[e]], 1);
}

// 256 blocks x 256 threads, 512 elems/block
__global__ void k_scanA() {
    __shared__ int sd[256];
    int b = blockIdx.x, t = threadIdx.x;
    int i = b * 512 + t * 2;
    int e0 = g_cnt[i], e1 = g_cnt[i + 1];
    int s = e0 + e1;
    sd[t] = s;
    __syncthreads();
#pragma unroll
    for (int off = 1; off < 256; off <<= 1) {
        int v = (t >= off) ? sd[t - off] : 0;
        __syncthreads();
        sd[t] += v;
        __syncthreads();
    }
    int incl = sd[t];
    int excl = incl - s;
    g_off[i]     = excl;
    g_off[i + 1] = excl + e0;
    if (t == 255) g_bs[b] = incl;
}

__global__ void k_scanB() {
    __shared__ int sd[256];
    int t = threadIdx.x;
    int v = g_bs[t];
    sd[t] = v;
    __syncthreads();
#pragma unroll
    for (int off = 1; off < 256; off <<= 1) {
        int x = (t >= off) ? sd[t - off] : 0;
        __syncthreads();
        sd[t] += x;
        __syncthreads();
    }
    g_bs[t] = sd[t] - v;   // exclusive
}

__global__ void k_scanC() {
    int b = blockIdx.x, t = threadIdx.x;
    int add = g_bs[b];
    int i = b * 512 + t * 2;
    int o0 = g_off[i] + add, o1 = g_off[i + 1] + add;
    g_off[i] = o0;  g_off[i + 1] = o1;
    g_cur[i] = o0;  g_cur[i + 1] = o1;
    if (b == 0 && t == 0) g_off[N_NODES] = N_EDGES;
}

__global__ void k_scatter(const float* __restrict__ pos,
                          const int* __restrict__ snd, const int* __restrict__ rcv) {
    int e = blockIdx.x * blockDim.x + threadIdx.x;
    if (e >= N_EDGES) return;
    int s = snd[e], r = rcv[e];
    float sx = pos[3*s+0], sy = pos[3*s+1], sz = pos[3*s+2];
    float rx = pos[3*r+0], ry = pos[3*r+1], rz = pos[3*r+2];
    float dx = rx - sx, dy = ry - sy, dz = rz - sz;
    float dist = sqrtf(dx*dx + dy*dy + dz*dz);
    float inv = 1.0f / fmaxf(dist, 1e-9f);
    int slot = atomicAdd(&g_cur[r], 1);
    g_src[slot] = s;
    g_geo[slot] = make_float4(dx * inv, dy * inv, dz * inv, dist);
}

// ---------------- layer gathers (one thread per receiver node) ---------------

// Layer 1: paths 0,1 ; fuse si2 + gate -> x0b, x1b
__global__ void k_gather1(const float* __restrict__ nf, const float* __restrict__ wsi1,
                          const float* __restrict__ rw1, const float* __restrict__ rb1,
                          const float* __restrict__ rw2, const float* __restrict__ rb2,
                          const float* __restrict__ w20, const float* __restrict__ w21) {
    LOAD_RADIAL_SMEM(rw1, rb1, rw2, rb2);
    __shared__ float s20[16], s21[16], s1[4];
    for (int i = threadIdx.x; i < 16; i += blockDim.x) { s20[i] = w20[i]; s21[i] = w21[i]; }
    if (threadIdx.x < 4) s1[threadIdx.x] = wsi1[threadIdx.x];
    __syncthreads();

    int n = blockIdx.x * blockDim.x + threadIdx.x;   // N_NODES % 256 == 0
    int beg = g_off[n], end = g_off[n + 1];
    float a0[4] = {0.f, 0.f, 0.f, 0.f};
    float a1[12];
#pragma unroll
    for (int i = 0; i < 12; i++) a1[i] = 0.f;

    for (int i = beg; i < end; i++) {
        int s = g_src[i];
        float4 g = g_geo[i];
        float rbf[8];
        rbf_from_dist(g.w, rbf);
        float R0[4], R1[4];
        radial(0, rbf, R0, sw1, sb1, sw2, sb2);
        radial(1, rbf, R1, sw1, sb1, sw2, sb2);
        float nfv = __ldg(&nf[s]);
#pragma unroll
        for (int c = 0; c < 4; c++) {
            float xs = s1[c] * nfv;
            a0[c] = fmaf(R0[c], xs, a0[c]);
            float t = R1[c] * xs;
            a1[c*3+0] = fmaf(t, g.x, a1[c*3+0]);
            a1[c*3+1] = fmaf(t, g.y, a1[c*3+1]);
            a1[c*3+2] = fmaf(t, g.z, a1[c*3+2]);
        }
    }

    // si2 + gate
    float out0[4];
#pragma unroll
    for (int o = 0; o < 4; o++) {
        float sacc = 0.f;
#pragma unroll
        for (int i = 0; i < 4; i++) sacc = fmaf(s20[o*4+i], a0[i], sacc);
        out0[o] = sacc * sigmoidf(sacc);
    }
    ((float4*)g_x0b)[n] = make_float4(out0[0], out0[1], out0[2], out0[3]);

    float out1[12];
#pragma unroll
    for (int o = 0; o < 4; o++) {
        float vx = 0.f, vy = 0.f, vz = 0.f;
#pragma unroll
        for (int i = 0; i < 4; i++) {
            float w = s21[o*4+i];
            vx = fmaf(w, a1[i*3+0], vx);
            vy = fmaf(w, a1[i*3+1], vy);
            vz = fmaf(w, a1[i*3+2], vz);
        }
        float nrm = sqrtf(vx*vx + vy*vy + vz*vz);
        float gt = sigmoidf(nrm);
        out1[o*3+0] = vx*gt; out1[o*3+1] = vy*gt; out1[o*3+2] = vz*gt;
    }
    ((float4*)g_x1b)[n*3+0] = make_float4(out1[0], out1[1], out1[2],  out1[3]);
    ((float4*)g_x1b)[n*3+1] = make_float4(out1[4], out1[5], out1[6],  out1[7]);
    ((float4*)g_x1b)[n*3+2] = make_float4(out1[8], out1[9], out1[10], out1[11]);
}

// Layer 2: paths 2..6 ; fuse si3 + gate -> x0c, x1c
__global__ void k_gather2(const float* __restrict__ rw1, const float* __restrict__ rb1,
                          const float* __restrict__ rw2, const float* __restrict__ rb2,
                          const float* __restrict__ w30, const float* __restrict__ w31) {
    LOAD_RADIAL_SMEM(rw1, rb1, rw2, rb2);
    __shared__ float s30[32], s31[48];
    for (int i = threadIdx.x; i < 32; i += blockDim.x) s30[i] = w30[i];
    for (int i = threadIdx.x; i < 48; i += blockDim.x) s31[i] = w31[i];
    __syncthreads();

    int n = blockIdx.x * blockDim.x + threadIdx.x;
    int beg = g_off[n], end = g_off[n + 1];
    float b0[8];
    float b1[36];
#pragma unroll
    for (int i = 0; i < 8; i++)  b0[i] = 0.f;
#pragma unroll
    for (int i = 0; i < 36; i++) b1[i] = 0.f;

    for (int i = beg; i < end; i++) {
        int s = g_src[i];
        float4 g = g_geo[i];
        float ux = g.x, uy = g.y, uz = g.z;
        float rbf[8];
        rbf_from_dist(g.w, rbf);

        float4 x0 = ((const float4*)g_x0b)[s];
        float xs[4] = {x0.x, x0.y, x0.z, x0.w};
        float x1[12];
        {
            float4 t0 = ((const float4*)g_x1b)[s*3+0];
            float4 t1 = ((const float4*)g_x1b)[s*3+1];
            float4 t2 = ((const float4*)g_x1b)[s*3+2];
            x1[0]=t0.x; x1[1]=t0.y; x1[2]=t0.z; x1[3]=t0.w;
            x1[4]=t1.x; x1[5]=t1.y; x1[6]=t1.z; x1[7]=t1.w;
            x1[8]=t2.x; x1[9]=t2.y; x1[10]=t2.z; x1[11]=t2.w;
        }

        float R[4];
        // p00_0 : R2 * x0s -> b0[0:4]
        radial(2, rbf, R, sw1, sb1, sw2, sb2);
#pragma unroll
        for (int c = 0; c < 4; c++) b0[c] = fmaf(R[c], xs[c], b0[c]);

        // p11_0 : R5 * (x1s . u)/sqrt3 -> b0[4:8]
        radial(5, rbf, R, sw1, sb1, sw2, sb2);
#pragma unroll
        for (int c = 0; c < 4; c++) {
            float d = x1[c*3+0]*ux + x1[c*3+1]*uy + x1[c*3+2]*uz;
            b0[4+c] = fmaf(R[c] * INV_SQRT3, d, b0[4+c]);
        }

        // p01_1 : R3 * x0s * u -> b1[0..11]
        radial(3, rbf, R, sw1, sb1, sw2, sb2);
#pragma unroll
        for (int c = 0; c < 4; c++) {
            float t = R[c] * xs[c];
            b1[c*3+0] = fmaf(t, ux, b1[c*3+0]);
            b1[c*3+1] = fmaf(t, uy, b1[c*3+1]);
            b1[c*3+2] = fmaf(t, uz, b1[c*3+2]);
        }
        // p10_1 : R4 * x1s -> b1[12..23]
        radial(4, rbf, R, sw1, sb1, sw2, sb2);
#pragma unroll
        for (int c = 0; c < 4; c++) {
            b1[12+c*3+0] = fmaf(R[c], x1[c*3+0], b1[12+c*3+0]);
            b1[12+c*3+1] = fmaf(R[c], x1[c*3+1], b1[12+c*3+1]);
            b1[12+c*3+2] = fmaf(R[c], x1[c*3+2], b1[12+c*3+2]);
        }
        // p11_1 : R6 * cross(x1s,u)/sqrt2 -> b1[24..35]
        radial(6, rbf, R, sw1, sb1, sw2, sb2);
#pragma unroll
        for (int c = 0; c < 4; c++) {
            float ax = x1[c*3+0], ay = x1[c*3+1], az = x1[c*3+2];
            float cx = ay*uz - az*uy;
            float cy = az*ux - ax*uz;
            float cz = ax*uy - ay*ux;
            float t = R[c] * INV_SQRT2;
            b1[24+c*3+0] = fmaf(t, cx, b1[24+c*3+0]);
            b1[24+c*3+1] = fmaf(t, cy, b1[24+c*3+1]);
            b1[24+c*3+2] = fmaf(t, cz, b1[24+c*3+2]);
        }
    }

    // si3 + gate
    float out0[4];
#pragma unroll
    for (int o = 0; o < 4; o++) {
        float sacc = 0.f;
#pragma unroll
        for (int i = 0; i < 8; i++) sacc = fmaf(s30[o*8+i], b0[i], sacc);
        out0[o] = sacc * sigmoidf(sacc);
    }
    ((float4*)g_x0c)[n] = make_float4(out0[0], out0[1], out0[2], out0[3]);

    // b1 layout here: channel index = [p01 c0..3 | p10 c0..3 | p11 c0..3], each x3 comps
    float out1[12];
#pragma unroll
    for (int o = 0; o < 4; o++) {
        float vx = 0.f, vy = 0.f, vz = 0.f;
#pragma unroll
        for (int i = 0; i < 12; i++) {
            float w = s31[o*12+i];
            vx = fmaf(w, b1[i*3+0], vx);
            vy = fmaf(w, b1[i*3+1], vy);
            vz = fmaf(w, b1[i*3+2], vz);
        }
        float nrm = sqrtf(vx*vx + vy*vy + vz*vz);
        float gt = sigmoidf(nrm);
        out1[o*3+0]=vx*gt; out1[o*3+1]=vy*gt; out1[o*3+2]=vz*gt;
    }
    ((float4*)g_x1c)[n*3+0] = make_float4(out1[0], out1[1], out1[2],  out1[3]);
    ((float4*)g_x1c)[n*3+1] = make_float4(out1[4], out1[5], out1[6],  out1[7]);
    ((float4*)g_x1c)[n*3+2] = make_float4(out1[8], out1[9], out1[10], out1[11]);
}

// Layer 3: paths 7,8 ; fuse si4 + silu -> f (4 per node)
__global__ void k_gather3(const float* __restrict__ rw1, const float* __restrict__ rb1,
                          const float* __restrict__ rw2, const float* __restrict__ rb2,
                          const float* __restrict__ w4) {
    LOAD_RADIAL_SMEM(rw1, rb1, rw2, rb2);
    __shared__ float s4[32];
    for (int i = threadIdx.x; i < 32; i += blockDim.x) s4[i] = w4[i];
    __syncthreads();

    int n = blockIdx.x * blockDim.x + threadIdx.x;
    int beg = g_off[n], end = g_off[n + 1];
    float c0[8];
#pragma unroll
    for (int i = 0; i < 8; i++) c0[i] = 0.f;

    for (int i = beg; i < end; i++) {
        int s = g_src[i];
        float4 g = g_geo[i];
        float rbf[8];
        rbf_from_dist(g.w, rbf);
        float R[4];

        float4 x0 = ((const float4*)g_x0c)[s];
        radial(7, rbf, R, sw1, sb1, sw2, sb2);
        c0[0] = fmaf(R[0], x0.x, c0[0]);
        c0[1] = fmaf(R[1], x0.y, c0[1]);
        c0[2] = fmaf(R[2], x0.z, c0[2]);
        c0[3] = fmaf(R[3], x0.w, c0[3]);

        radial(8, rbf, R, sw1, sb1, sw2, sb2);
        float4 t0 = ((const float4*)g_x1c)[s*3+0];
        float4 t1 = ((const float4*)g_x1c)[s*3+1];
        float4 t2 = ((const float4*)g_x1c)[s*3+2];
        float d0 = t0.x*g.x + t0.y*g.y + t0.z*g.z;
        float d1 = t0.w*g.x + t1.x*g.y + t1.y*g.z;
        float d2 = t1.z*g.x + t1.w*g.y + t2.x*g.z;
        float d3 = t2.y*g.x + t2.z*g.y + t2.w*g.z;
        c0[4] = fmaf(R[0] * INV_SQRT3, d0, c0[4]);
        c0[5] = fmaf(R[1] * INV_SQRT3, d1, c0[5]);
        c0[6] = fmaf(R[2] * INV_SQRT3, d2, c0[6]);
        c0[7] = fmaf(R[3] * INV_SQRT3, d3, c0[7]);
    }

    float f[4];
#pragma unroll
    for (int o = 0; o < 4; o++) {
        float sacc = 0.f;
#pragma unroll
        for (int i = 0; i < 8; i++) sacc = fmaf(s4[o*8+i], c0[i], sacc);
        f[o] = sacc * sigmoidf(sacc);
    }
    ((float4*)g_f)[n] = make_float4(f[0], f[1], f[2], f[3]);
}

// readout: warp-reduce 32 nodes/graph, apply w_out
__global__ void k_final(const float* __restrict__ wout, float* __restrict__ out) {
    int gw = (blockIdx.x * blockDim.x + threadIdx.x) >> 5;
    int lane = threadIdx.x & 31;
    if (gw >= N_GRAPH) return;
    int n = gw * NPG + lane;
    float4 t = ((const float4*)g_f)[n];
    float f[4] = {t.x, t.y, t.z, t.w};
#pragma unroll
    for (int o = 0; o < 4; o++) {
#pragma unroll
        for (int off = 16; off > 0; off >>= 1)
            f[o] += __shfl_xor_sync(0xFFFFFFFFu, f[o], off);
    }
    if (lane < 8) {
        float acc = 0.f;
#pragma unroll
        for (int o = 0; o < 4; o++) acc = fmaf(__ldg(&wout[lane*4+o]), f[o], acc);
        out[gw*8 + lane] = acc;
    }
}

// ---------------- launch ----------------------------------------------------
extern "C" void kernel_launch(void* const* d_in, const int* in_sizes, int n_in,
                              void* d_out, int out_size) {
    const float* pos   = (const float*)d_in[0];
    const float* nf    = (const float*)d_in[1];
    const float* w_si1 = (const float*)d_in[2];
    const float* w20   = (const float*)d_in[3];
    const float* w21   = (const float*)d_in[4];
    const float* w30   = (const float*)d_in[5];
    const float* w31   = (const float*)d_in[6];
    const float* w4    = (const float*)d_in[7];
    const float* wout  = (const float*)d_in[8];
    const float* rw1   = (const float*)d_in[9];
    const float* rb1   = (const float*)d_in[10];
    const float* rw2   = (const float*)d_in[11];
    const float* rb2   = (const float*)d_in[12];
    const int*   snd   = (const int*)d_in[13];
    const int*   rcv   = (const int*)d_in[14];
    float* out = (float*)d_out;

    const int TB = 256;
    // CSR build
    k_zero   <<<(N_NODES/4 + TB - 1)/TB, TB>>>();
    k_hist   <<<N_EDGES/TB, TB>>>(rcv);
    k_scanA  <<<256, 256>>>();
    k_scanB  <<<1, 256>>>();
    k_scanC  <<<256, 256>>>();
    k_scatter<<<N_EDGES/TB, TB>>>(pos, snd, rcv);
    // layers (pull-gather, fused node updates)
    k_gather1<<<N_NODES/TB, TB>>>(nf, w_si1, rw1, rb1, rw2, rb2, w20, w21);
    k_gather2<<<N_NODES/TB, TB>>>(rw1, rb1, rw2, rb2, w30, w31);
    k_gather3<<<N_NODES/TB, TB>>>(rw1, rb1, rw2, rb2, w4);
    k_final  <<<(N_GRAPH * 32)/TB, TB>>>(wout, out);
}

// round 5
// speedup vs baseline: 2.7096x; 2.7096x over previous
#include <cuda_runtime.h>
#include <cstdint>

#define N_GRAPH   4096
#define NPG       32
#define N_NODES   (N_GRAPH * NPG)      // 131072
#define N_EDGES   (N_NODES * 16)       // 2097152
#define INV_SQRT3 0.57735026918962576451f
#define INV_SQRT2 0.70710678118654752440f
#define FULLM     0xFFFFFFFFu

// ---------------- scratch (static device arrays) -----------------------------
__device__ int   g_cnt[N_NODES];
__device__ int   g_off[N_NODES + 1];
__device__ int   g_cur[N_NODES];
__device__ int   g_bs [256];
__device__ int   g_src[N_EDGES];          // sender, receiver-sorted
__device__ int   g_key[N_EDGES];          // receiver, receiver-sorted
__device__ __align__(16) float4 g_geo[N_EDGES];   // ux,uy,uz,dist

__device__ __align__(16) float g_a0 [N_NODES * 4];
__device__ __align__(16) float g_a1 [N_NODES * 12];
__device__ __align__(16) float g_x0b[N_NODES * 4];
__device__ __align__(16) float g_x1b[N_NODES * 12];
__device__ __align__(16) float g_b0 [N_NODES * 8];
__device__ __align__(16) float g_b1 [N_NODES * 36];
__device__ __align__(16) float g_x0c[N_NODES * 4];
__device__ __align__(16) float g_x1c[N_NODES * 12];
__device__ __align__(16) float g_c0 [N_NODES * 8];

// ---------------- helpers ---------------------------------------------------
__device__ __forceinline__ void red4(float* p, float a, float b, float c, float d) {
    asm volatile("red.global.add.v4.f32 [%0], {%1,%2,%3,%4};"
                 :: "l"(p), "f"(a), "f"(b), "f"(c), "f"(d) : "memory");
}

__device__ __forceinline__ float sigmoidf(float x) {
    return 1.0f / (1.0f + __expf(-x));
}

__device__ __forceinline__ void rbf_from_dist(float dist, float rbf[8]) {
#pragma unroll
    for (int b = 0; b < 8; b++) {
        float t = dist - 0.5f * (float)b;          // centers = linspace(0,3.5,8)
        rbf[b] = __expf(-4.0f * t * t);
    }
}

// one radial path: R[4] = relu(rbf @ w1[p] + b1[p]) @ w2[p] + b2[p]
__device__ __forceinline__ void radial(int p, const float rbf[8], float R[4],
                                       const float* sw1, const float* sb1,
                                       const float* sw2, const float* sb2) {
    float h[8];
    const float* w1 = sw1 + p * 64;
#pragma unroll
    for (int j = 0; j < 8; j++) h[j] = sb1[p*8 + j];
#pragma unroll
    for (int b = 0; b < 8; b++) {
        float rb = rbf[b];
#pragma unroll
        for (int j = 0; j < 8; j++) h[j] = fmaf(rb, w1[b*8 + j], h[j]);
    }
#pragma unroll
    for (int j = 0; j < 8; j++) h[j] = fmaxf(h[j], 0.0f);
    const float* w2 = sw2 + p * 32;
#pragma unroll
    for (int c = 0; c < 4; c++) R[c] = sb2[p*4 + c];
#pragma unroll
    for (int j = 0; j < 8; j++) {
        float hj = h[j];
#pragma unroll
        for (int c = 0; c < 4; c++) R[c] = fmaf(hj, w2[j*4 + c], R[c]);
    }
}

#define LOAD_RADIAL_SMEM(rw1, rb1, rw2, rb2)                                   \
    __shared__ float sw1[576], sb1[72], sw2[288], sb2[36];                     \
    for (int i = threadIdx.x; i < 576; i += blockDim.x) sw1[i] = rw1[i];       \
    for (int i = threadIdx.x; i < 72;  i += blockDim.x) sb1[i] = rb1[i];       \
    for (int i = threadIdx.x; i < 288; i += blockDim.x) sw2[i] = rw2[i];       \
    for (int i = threadIdx.x; i < 36;  i += blockDim.x) sb2[i] = rb2[i];       \
    __syncthreads();

// ---------------- init: zero counters + accumulators -------------------------
__global__ void k_init() {
    long i0 = (long)blockIdx.x * blockDim.x + threadIdx.x;
    long stride = (long)gridDim.x * blockDim.x;
    for (long i = i0; i < N_NODES / 4; i += stride)
        ((int4*)g_cnt)[i] = make_int4(0, 0, 0, 0);
    float4 z = make_float4(0.f, 0.f, 0.f, 0.f);
    for (long i = i0; i < N_NODES;     i += stride) ((float4*)g_a0)[i] = z;
    for (long i = i0; i < N_NODES * 3; i += stride) ((float4*)g_a1)[i] = z;
    for (long i = i0; i < N_NODES * 2; i += stride) ((float4*)g_b0)[i] = z;
    for (long i = i0; i < N_NODES * 9; i += stride) ((float4*)g_b1)[i] = z;
    for (long i = i0; i < N_NODES * 2; i += stride) ((float4*)g_c0)[i] = z;
}

// ---------------- CSR build --------------------------------------------------
__global__ void k_hist(const int* __restrict__ rcv) {
    int e = blockIdx.x * blockDim.x + threadIdx.x;
    if (e < N_EDGES) atomicAdd(&g_cnt[rcv[e]], 1);
}

// 256 blocks x 256 threads, 512 elems/block
__global__ void k_scanA() {
    __shared__ int sd[256];
    int b = blockIdx.x, t = threadIdx.x;
    int i = b * 512 + t * 2;
    int e0 = g_cnt[i], e1 = g_cnt[i + 1];
    int s = e0 + e1;
    sd[t] = s;
    __syncthreads();
#pragma unroll
    for (int off = 1; off < 256; off <<= 1) {
        int v = (t >= off) ? sd[t - off] : 0;
        __syncthreads();
        sd[t] += v;
        __syncthreads();
    }
    int incl = sd[t];
    int excl = incl - s;
    g_off[i]     = excl;
    g_off[i + 1] = excl + e0;
    if (t == 255) g_bs[b] = incl;
}

__global__ void k_scanB() {
    __shared__ int sd[256];
    int t = threadIdx.x;
    int v = g_bs[t];
    sd[t] = v;
    __syncthreads();
#pragma unroll
    for (int off = 1; off < 256; off <<= 1) {
        int x = (t >= off) ? sd[t - off] : 0;
        __syncthreads();
        sd[t] += x;
        __syncthreads();
    }
    g_bs[t] = sd[t] - v;   // exclusive
}

__global__ void k_scanC() {
    int b = blockIdx.x, t = threadIdx.x;
    int add = g_bs[b];
    int i = b * 512 + t * 2;
    int o0 = g_off[i] + add, o1 = g_off[i + 1] + add;
    g_off[i] = o0;  g_off[i + 1] = o1;
    g_cur[i] = o0;  g_cur[i + 1] = o1;
    if (b == 0 && t == 0) g_off[N_NODES] = N_EDGES;
}

__global__ void k_scatter(const float* __restrict__ pos,
                          const int* __restrict__ snd, const int* __restrict__ rcv) {
    int e = blockIdx.x * blockDim.x + threadIdx.x;
    if (e >= N_EDGES) return;
    int s = snd[e], r = rcv[e];
    float sx = pos[3*s+0], sy = pos[3*s+1], sz = pos[3*s+2];
    float rx = pos[3*r+0], ry = pos[3*r+1], rz = pos[3*r+2];
    float dx = rx - sx, dy = ry - sy, dz = rz - sz;
    float dist = sqrtf(dx*dx + dy*dy + dz*dz);
    float inv = 1.0f / fmaxf(dist, 1e-9f);
    int slot = atomicAdd(&g_cur[r], 1);
    g_src[slot] = s;
    g_key[slot] = r;
    g_geo[slot] = make_float4(dx * inv, dy * inv, dz * inv, dist);
}

// ---------------- edge kernels (receiver-sorted, plain vector RED) -----------

// Layer 1: paths 0,1  (x0 = w_si1 * nf fused into the gather)
__global__ void k_edge1(const float* __restrict__ nf, const float* __restrict__ wsi1,
                        const float* __restrict__ rw1, const float* __restrict__ rb1,
                        const float* __restrict__ rw2, const float* __restrict__ rb2) {
    LOAD_RADIAL_SMEM(rw1, rb1, rw2, rb2);
    __shared__ float s1[4];
    if (threadIdx.x < 4) s1[threadIdx.x] = wsi1[threadIdx.x];
    __syncthreads();

    int e = blockIdx.x * blockDim.x + threadIdx.x;   // N_EDGES % 256 == 0
    int s = g_src[e];
    int r = g_key[e];
    float4 g = g_geo[e];

    float rbf[8];
    rbf_from_dist(g.w, rbf);
    float R0[4], R1[4];
    radial(0, rbf, R0, sw1, sb1, sw2, sb2);
    radial(1, rbf, R1, sw1, sb1, sw2, sb2);
    float nfv = __ldg(&nf[s]);
    float xs[4];
#pragma unroll
    for (int c = 0; c < 4; c++) xs[c] = s1[c] * nfv;

    red4(&g_a0[r*4], R0[0]*xs[0], R0[1]*xs[1], R0[2]*xs[2], R0[3]*xs[3]);

    float m[12];
#pragma unroll
    for (int c = 0; c < 4; c++) {
        float t = R1[c] * xs[c];
        m[c*3+0] = t*g.x; m[c*3+1] = t*g.y; m[c*3+2] = t*g.z;
    }
    red4(&g_a1[r*12+0], m[0], m[1], m[2],  m[3]);
    red4(&g_a1[r*12+4], m[4], m[5], m[6],  m[7]);
    red4(&g_a1[r*12+8], m[8], m[9], m[10], m[11]);
}

// node update 1: si2 + gate
__global__ void k_node1(const float* __restrict__ w20, const float* __restrict__ w21) {
    int n = blockIdx.x * blockDim.x + threadIdx.x;
    if (n >= N_NODES) return;
    float4 a0 = ((const float4*)g_a0)[n];
    float in0[4] = {a0.x, a0.y, a0.z, a0.w};
    float out0[4];
#pragma unroll
    for (int o = 0; o < 4; o++) {
        float sacc = 0.f;
#pragma unroll
        for (int i = 0; i < 4; i++) sacc = fmaf(__ldg(&w20[o*4+i]), in0[i], sacc);
        out0[o] = sacc * sigmoidf(sacc);
    }
    ((float4*)g_x0b)[n] = make_float4(out0[0], out0[1], out0[2], out0[3]);

    float a1[12];
    float4 t0 = ((const float4*)g_a1)[n*3+0];
    float4 t1 = ((const float4*)g_a1)[n*3+1];
    float4 t2 = ((const float4*)g_a1)[n*3+2];
    a1[0]=t0.x; a1[1]=t0.y; a1[2]=t0.z; a1[3]=t0.w;
    a1[4]=t1.x; a1[5]=t1.y; a1[6]=t1.z; a1[7]=t1.w;
    a1[8]=t2.x; a1[9]=t2.y; a1[10]=t2.z; a1[11]=t2.w;
    float out1[12];
#pragma unroll
    for (int o = 0; o < 4; o++) {
        float vx = 0.f, vy = 0.f, vz = 0.f;
#pragma unroll
        for (int i = 0; i < 4; i++) {
            float w = __ldg(&w21[o*4+i]);
            vx = fmaf(w, a1[i*3+0], vx);
            vy = fmaf(w, a1[i*3+1], vy);
            vz = fmaf(w, a1[i*3+2], vz);
        }
        float nrm = sqrtf(vx*vx + vy*vy + vz*vz);
        float gt = sigmoidf(nrm);
        out1[o*3+0] = vx*gt; out1[o*3+1] = vy*gt; out1[o*3+2] = vz*gt;
    }
    ((float4*)g_x1b)[n*3+0] = make_float4(out1[0], out1[1], out1[2],  out1[3]);
    ((float4*)g_x1b)[n*3+1] = make_float4(out1[4], out1[5], out1[6],  out1[7]);
    ((float4*)g_x1b)[n*3+2] = make_float4(out1[8], out1[9], out1[10], out1[11]);
}

// Layer 2: paths 2..6
__global__ void k_edge2(const float* __restrict__ rw1, const float* __restrict__ rb1,
                        const float* __restrict__ rw2, const float* __restrict__ rb2) {
    LOAD_RADIAL_SMEM(rw1, rb1, rw2, rb2);
    int e = blockIdx.x * blockDim.x + threadIdx.x;
    int s = g_src[e];
    int r = g_key[e];
    float4 g = g_geo[e];
    float ux = g.x, uy = g.y, uz = g.z;
    float rbf[8];
    rbf_from_dist(g.w, rbf);

    float4 x0 = ((const float4*)g_x0b)[s];
    float xs[4] = {x0.x, x0.y, x0.z, x0.w};
    float x1[12];
    {
        float4 t0 = ((const float4*)g_x1b)[s*3+0];
        float4 t1 = ((const float4*)g_x1b)[s*3+1];
        float4 t2 = ((const float4*)g_x1b)[s*3+2];
        x1[0]=t0.x; x1[1]=t0.y; x1[2]=t0.z; x1[3]=t0.w;
        x1[4]=t1.x; x1[5]=t1.y; x1[6]=t1.z; x1[7]=t1.w;
        x1[8]=t2.x; x1[9]=t2.y; x1[10]=t2.z; x1[11]=t2.w;
    }

    float R[4];
    // p00_0 : R2 * x0s -> b0[0:4]
    radial(2, rbf, R, sw1, sb1, sw2, sb2);
    red4(&g_b0[r*8], R[0]*xs[0], R[1]*xs[1], R[2]*xs[2], R[3]*xs[3]);

    // p11_0 : R5 * (x1s . u)/sqrt3 -> b0[4:8]
    radial(5, rbf, R, sw1, sb1, sw2, sb2);
    {
        float d0 = x1[0]*ux + x1[1]*uy + x1[2]*uz;
        float d1 = x1[3]*ux + x1[4]*uy + x1[5]*uz;
        float d2 = x1[6]*ux + x1[7]*uy + x1[8]*uz;
        float d3 = x1[9]*ux + x1[10]*uy + x1[11]*uz;
        red4(&g_b0[r*8+4], R[0]*d0*INV_SQRT3, R[1]*d1*INV_SQRT3,
                           R[2]*d2*INV_SQRT3, R[3]*d3*INV_SQRT3);
    }

    float* b1base = &g_b1[r*36];
    // p01_1 : R3 * x0s * u -> b1[0..11]
    radial(3, rbf, R, sw1, sb1, sw2, sb2);
    {
        float m[12];
#pragma unroll
        for (int c = 0; c < 4; c++) {
            float t = R[c] * xs[c];
            m[c*3+0]=t*ux; m[c*3+1]=t*uy; m[c*3+2]=t*uz;
        }
        red4(b1base+0, m[0],m[1],m[2], m[3]);
        red4(b1base+4, m[4],m[5],m[6], m[7]);
        red4(b1base+8, m[8],m[9],m[10],m[11]);
    }
    // p10_1 : R4 * x1s -> b1[12..23]
    radial(4, rbf, R, sw1, sb1, sw2, sb2);
    {
        float m[12];
#pragma unroll
        for (int c = 0; c < 4; c++) {
            m[c*3+0]=R[c]*x1[c*3+0]; m[c*3+1]=R[c]*x1[c*3+1]; m[c*3+2]=R[c]*x1[c*3+2];
        }
        red4(b1base+12, m[0],m[1],m[2], m[3]);
        red4(b1base+16, m[4],m[5],m[6], m[7]);
        red4(b1base+20, m[8],m[9],m[10],m[11]);
    }
    // p11_1 : R6 * cross(x1s,u)/sqrt2 -> b1[24..35]
    radial(6, rbf, R, sw1, sb1, sw2, sb2);
    {
        float m[12];
#pragma unroll
        for (int c = 0; c < 4; c++) {
            float ax = x1[c*3+0], ay = x1[c*3+1], az = x1[c*3+2];
            float cx = ay*uz - az*uy;
            float cy = az*ux - ax*uz;
            float cz = ax*uy - ay*ux;
            float t = R[c] * INV_SQRT2;
            m[c*3+0]=t*cx; m[c*3+1]=t*cy; m[c*3+2]=t*cz;
        }
        red4(b1base+24, m[0],m[1],m[2], m[3]);
        red4(b1base+28, m[4],m[5],m[6], m[7]);
        red4(b1base+32, m[8],m[9],m[10],m[11]);
    }
}

// node update 2: si3 + gate
__global__ void k_node2(const float* __restrict__ w30, const float* __restrict__ w31) {
    int n = blockIdx.x * blockDim.x + threadIdx.x;
    if (n >= N_NODES) return;
    float b0[8];
    {
        float4 t0 = ((const float4*)g_b0)[n*2+0];
        float4 t1 = ((const float4*)g_b0)[n*2+1];
        b0[0]=t0.x; b0[1]=t0.y; b0[2]=t0.z; b0[3]=t0.w;
        b0[4]=t1.x; b0[5]=t1.y; b0[6]=t1.z; b0[7]=t1.w;
    }
    float out0[4];
#pragma unroll
    for (int o = 0; o < 4; o++) {
        float sacc = 0.f;
#pragma unroll
        for (int i = 0; i < 8; i++) sacc = fmaf(__ldg(&w30[o*8+i]), b0[i], sacc);
        out0[o] = sacc * sigmoidf(sacc);
    }
    ((float4*)g_x0c)[n] = make_float4(out0[0], out0[1], out0[2], out0[3]);

    float b1[36];
#pragma unroll
    for (int q = 0; q < 9; q++) {
        float4 t = ((const float4*)g_b1)[n*9+q];
        b1[q*4+0]=t.x; b1[q*4+1]=t.y; b1[q*4+2]=t.z; b1[q*4+3]=t.w;
    }
    float out1[12];
#pragma unroll
    for (int o = 0; o < 4; o++) {
        float vx = 0.f, vy = 0.f, vz = 0.f;
#pragma unroll
        for (int i = 0; i < 12; i++) {
            float w = __ldg(&w31[o*12+i]);
            vx = fmaf(w, b1[i*3+0], vx);
            vy = fmaf(w, b1[i*3+1], vy);
            vz = fmaf(w, b1[i*3+2], vz);
        }
        float nrm = sqrtf(vx*vx + vy*vy + vz*vz);
        float gt = sigmoidf(nrm);
        out1[o*3+0]=vx*gt; out1[o*3+1]=vy*gt; out1[o*3+2]=vz*gt;
    }
    ((float4*)g_x1c)[n*3+0] = make_float4(out1[0], out1[1], out1[2],  out1[3]);
    ((float4*)g_x1c)[n*3+1] = make_float4(out1[4], out1[5], out1[6],  out1[7]);
    ((float4*)g_x1c)[n*3+2] = make_float4(out1[8], out1[9], out1[10], out1[11]);
}

// Layer 3: paths 7, 8
__global__ void k_edge3(const float* __restrict__ rw1, const float* __restrict__ rb1,
                        const float* __restrict__ rw2, const float* __restrict__ rb2) {
    LOAD_RADIAL_SMEM(rw1, rb1, rw2, rb2);
    int e = blockIdx.x * blockDim.x + threadIdx.x;
    int s = g_src[e];
    int r = g_key[e];
    float4 g = g_geo[e];

    float rbf[8];
    rbf_from_dist(g.w, rbf);
    float R[4];

    float4 x0 = ((const float4*)g_x0c)[s];
    radial(7, rbf, R, sw1, sb1, sw2, sb2);
    red4(&g_c0[r*8], R[0]*x0.x, R[1]*x0.y, R[2]*x0.z, R[3]*x0.w);

    radial(8, rbf, R, sw1, sb1, sw2, sb2);
    float4 t0 = ((const float4*)g_x1c)[s*3+0];
    float4 t1 = ((const float4*)g_x1c)[s*3+1];
    float4 t2 = ((const float4*)g_x1c)[s*3+2];
    float d0 = t0.x*g.x + t0.y*g.y + t0.z*g.z;
    float d1 = t0.w*g.x + t1.x*g.y + t1.y*g.z;
    float d2 = t1.z*g.x + t1.w*g.y + t2.x*g.z;
    float d3 = t2.y*g.x + t2.z*g.y + t2.w*g.z;
    red4(&g_c0[r*8+4], R[0]*d0*INV_SQRT3, R[1]*d1*INV_SQRT3,
                       R[2]*d2*INV_SQRT3, R[3]*d3*INV_SQRT3);
}

// readout: per-node si4 + silu, warp-reduce 32 nodes/graph, apply w_out
__global__ void k_final(const float* __restrict__ w4, const float* __restrict__ wout,
                        float* __restrict__ out) {
    int gw = (blockIdx.x * blockDim.x + threadIdx.x) >> 5;
    int lane = threadIdx.x & 31;
    if (gw >= N_GRAPH) return;
    int n = gw * NPG + lane;
    float c0[8];
    {
        float4 t0 = ((const float4*)g_c0)[n*2+0];
        float4 t1 = ((const float4*)g_c0)[n*2+1];
        c0[0]=t0.x; c0[1]=t0.y; c0[2]=t0.z; c0[3]=t0.w;
        c0[4]=t1.x; c0[5]=t1.y; c0[6]=t1.z; c0[7]=t1.w;
    }
    float f[4];
#pragma unroll
    for (int o = 0; o < 4; o++) {
        float sacc = 0.f;
#pragma unroll
        for (int i = 0; i < 8; i++) sacc = fmaf(__ldg(&w4[o*8+i]), c0[i], sacc);
        f[o] = sacc * sigmoidf(sacc);
    }
#pragma unroll
    for (int o = 0; o < 4; o++) {
#pragma unroll
        for (int off = 16; off > 0; off >>= 1)
            f[o] += __shfl_xor_sync(FULLM, f[o], off);
    }
    if (lane < 8) {
        float acc = 0.f;
#pragma unroll
        for (int o = 0; o < 4; o++) acc = fmaf(__ldg(&wout[lane*4+o]), f[o], acc);
        out[gw*8 + lane] = acc;
    }
}

// ---------------- launch ----------------------------------------------------
extern "C" void kernel_launch(void* const* d_in, const int* in_sizes, int n_in,
                              void* d_out, int out_size) {
    const float* pos   = (const float*)d_in[0];
    const float* nf    = (const float*)d_in[1];
    const float* w_si1 = (const float*)d_in[2];
    const float* w20   = (const float*)d_in[3];
    const float* w21   = (const float*)d_in[4];
    const float* w30   = (const float*)d_in[5];
    const float* w31   = (const float*)d_in[6];
    const float* w4    = (const float*)d_in[7];
    const float* wout  = (const float*)d_in[8];
    const float* rw1   = (const float*)d_in[9];
    const float* rb1   = (const float*)d_in[10];
    const float* rw2   = (const float*)d_in[11];
    const float* rb2   = (const float*)d_in[12];
    const int*   snd   = (const int*)d_in[13];
    const int*   rcv   = (const int*)d_in[14];
    float* out = (float*)d_out;

    const int TB = 256;
    k_init   <<<2048, TB>>>();
    k_hist   <<<N_EDGES/TB, TB>>>(rcv);
    k_scanA  <<<256, 256>>>();
    k_scanB  <<<1, 256>>>();
    k_scanC  <<<256, 256>>>();
    k_scatter<<<N_EDGES/TB, TB>>>(pos, snd, rcv);
    k_edge1  <<<N_EDGES/TB, TB>>>(nf, w_si1, rw1, rb1, rw2, rb2);
    k_node1  <<<N_NODES/TB, TB>>>(w20, w21);
    k_edge2  <<<N_EDGES/TB, TB>>>(rw1, rb1, rw2, rb2);
    k_node2  <<<N_NODES/TB, TB>>>(w30, w31);
    k_edge3  <<<N_EDGES/TB, TB>>>(rw1, rb1, rw2, rb2);
    k_final  <<<(N_GRAPH * 32)/TB, TB>>>(w4, wout, out);
}

// round 6
// speedup vs baseline: 3.1768x; 1.1724x over previous
#include <cuda_runtime.h>
#include <cstdint>

#define N_GRAPH   4096
#define NPG       32
#define N_NODES   (N_GRAPH * NPG)      // 131072
#define N_EDGES   (N_NODES * 16)       // 2097152
#define INV_SQRT3 0.57735026918962576451f
#define INV_SQRT2 0.70710678118654752440f
#define FULLM     0xFFFFFFFFu

// ---------------- scratch (static device arrays) -----------------------------
__device__ int   g_cnt[N_NODES];
__device__ int   g_off[N_NODES + 1];
__device__ int   g_cur[N_NODES];
__device__ int   g_bs [256];
__device__ __align__(8)  int2   g_sk [N_EDGES];   // {sender, receiver}, receiver-sorted
__device__ __align__(16) float4 g_geo[N_EDGES];   // ux,uy,uz,dist

__device__ __align__(16) float g_a0 [N_NODES * 4];
__device__ __align__(16) float g_a1 [N_NODES * 12];
__device__ __align__(16) float g_x0b[N_NODES * 4];
__device__ __align__(16) float g_x1b[N_NODES * 12];
__device__ __align__(16) float g_b0 [N_NODES * 8];
__device__ __align__(16) float g_b1 [N_NODES * 36];
__device__ __align__(16) float g_x0c[N_NODES * 4];
__device__ __align__(16) float g_x1c[N_NODES * 12];
__device__ __align__(16) float g_c0 [N_NODES * 8];

// ---------------- helpers ---------------------------------------------------
__device__ __forceinline__ void red4(float* p, float a, float b, float c, float d) {
    asm volatile("red.global.add.v4.f32 [%0], {%1,%2,%3,%4};"
                 :: "l"(p), "f"(a), "f"(b), "f"(c), "f"(d) : "memory");
}

__device__ __forceinline__ float sigmoidf(float x) {
    return 1.0f / (1.0f + __expf(-x));
}

__device__ __forceinline__ void rbf_from_dist(float dist, float rbf[8]) {
#pragma unroll
    for (int b = 0; b < 8; b++) {
        float t = dist - 0.5f * (float)b;          // centers = linspace(0,3.5,8)
        rbf[b] = __expf(-4.0f * t * t);
    }
}

// one radial path: R[4] = relu(rbf @ w1[p] + b1[p]) @ w2[p] + b2[p]
__device__ __forceinline__ void radial(int p, const float rbf[8], float R[4],
                                       const float* sw1, const float* sb1,
                                       const float* sw2, const float* sb2) {
    float h[8];
    const float* w1 = sw1 + p * 64;
#pragma unroll
    for (int j = 0; j < 8; j++) h[j] = sb1[p*8 + j];
#pragma unroll
    for (int b = 0; b < 8; b++) {
        float rb = rbf[b];
#pragma unroll
        for (int j = 0; j < 8; j++) h[j] = fmaf(rb, w1[b*8 + j], h[j]);
    }
#pragma unroll
    for (int j = 0; j < 8; j++) h[j] = fmaxf(h[j], 0.0f);
    const float* w2 = sw2 + p * 32;
#pragma unroll
    for (int c = 0; c < 4; c++) R[c] = sb2[p*4 + c];
#pragma unroll
    for (int j = 0; j < 8; j++) {
        float hj = h[j];
#pragma unroll
        for (int c = 0; c < 4; c++) R[c] = fmaf(hj, w2[j*4 + c], R[c]);
    }
}

// segmented warp sum of 4 values over contiguous equal-receiver runs.
// p[i]: lane+2^i is within this lane's segment. Heads issue the vector RED.
__device__ __forceinline__ void segred4(float v0, float v1, float v2, float v3,
                                        const bool p[5], bool head, float* addr) {
#pragma unroll
    for (int i = 0, off = 1; i < 5; i++, off <<= 1) {
        float t0 = __shfl_down_sync(FULLM, v0, off);
        float t1 = __shfl_down_sync(FULLM, v1, off);
        float t2 = __shfl_down_sync(FULLM, v2, off);
        float t3 = __shfl_down_sync(FULLM, v3, off);
        if (p[i]) { v0 += t0; v1 += t1; v2 += t2; v3 += t3; }
    }
    if (head) red4(addr, v0, v1, v2, v3);
}

// per-edge-warp segment setup from sorted receiver id r
#define SEG_SETUP()                                                            \
    int lane = threadIdx.x & 31;                                               \
    uint32_t seg = __match_any_sync(FULLM, r);                                 \
    bool head = (lane == (__ffs(seg) - 1));                                    \
    bool p[5];                                                                 \
    {                                                                          \
        _Pragma("unroll")                                                      \
        for (int i = 0, off = 1; i < 5; i++, off <<= 1) {                      \
            int ln = lane + off;                                               \
            p[i] = (ln < 32) && ((seg >> ln) & 1u);                            \
        }                                                                      \
    }

#define LOAD_RADIAL_SMEM(rw1, rb1, rw2, rb2)                                   \
    __shared__ float sw1[576], sb1[72], sw2[288], sb2[36];                     \
    for (int i = threadIdx.x; i < 576; i += blockDim.x) sw1[i] = rw1[i];       \
    for (int i = threadIdx.x; i < 72;  i += blockDim.x) sb1[i] = rb1[i];       \
    for (int i = threadIdx.x; i < 288; i += blockDim.x) sw2[i] = rw2[i];       \
    for (int i = threadIdx.x; i < 36;  i += blockDim.x) sb2[i] = rb2[i];       \
    __syncthreads();

// ---------------- init: zero counters + accumulators -------------------------
__global__ void k_init() {
    long i0 = (long)blockIdx.x * blockDim.x + threadIdx.x;
    long stride = (long)gridDim.x * blockDim.x;
    for (long i = i0; i < N_NODES / 4; i += stride)
        ((int4*)g_cnt)[i] = make_int4(0, 0, 0, 0);
    float4 z = make_float4(0.f, 0.f, 0.f, 0.f);
    for (long i = i0; i < N_NODES;     i += stride) ((float4*)g_a0)[i] = z;
    for (long i = i0; i < N_NODES * 3; i += stride) ((float4*)g_a1)[i] = z;
    for (long i = i0; i < N_NODES * 2; i += stride) ((float4*)g_b0)[i] = z;
    for (long i = i0; i < N_NODES * 9; i += stride) ((float4*)g_b1)[i] = z;
    for (long i = i0; i < N_NODES * 2; i += stride) ((float4*)g_c0)[i] = z;
}

// ---------------- CSR build --------------------------------------------------
__global__ void k_hist(const int* __restrict__ rcv) {
    int e = blockIdx.x * blockDim.x + threadIdx.x;
    if (e < N_EDGES) atomicAdd(&g_cnt[rcv[e]], 1);
}

// 256 blocks x 256 threads, 512 elems/block
__global__ void k_scanA() {
    __shared__ int sd[256];
    int b = blockIdx.x, t = threadIdx.x;
    int i = b * 512 + t * 2;
    int e0 = g_cnt[i], e1 = g_cnt[i + 1];
    int s = e0 + e1;
    sd[t] = s;
    __syncthreads();
#pragma unroll
    for (int off = 1; off < 256; off <<= 1) {
        int v = (t >= off) ? sd[t - off] : 0;
        __syncthreads();
        sd[t] += v;
        __syncthreads();
    }
    int incl = sd[t];
    int excl = incl - s;
    g_off[i]     = excl;
    g_off[i + 1] = excl + e0;
    if (t == 255) g_bs[b] = incl;
}

__global__ void k_scanB() {
    __shared__ int sd[256];
    int t = threadIdx.x;
    int v = g_bs[t];
    sd[t] = v;
    __syncthreads();
#pragma unroll
    for (int off = 1; off < 256; off <<= 1) {
        int x = (t >= off) ? sd[t - off] : 0;
        __syncthreads();
        sd[t] += x;
        __syncthreads();
    }
    g_bs[t] = sd[t] - v;   // exclusive
}

__global__ void k_scanC() {
    int b = blockIdx.x, t = threadIdx.x;
    int add = g_bs[b];
    int i = b * 512 + t * 2;
    int o0 = g_off[i] + add, o1 = g_off[i + 1] + add;
    g_off[i] = o0;  g_off[i + 1] = o1;
    g_cur[i] = o0;  g_cur[i + 1] = o1;
    if (b == 0 && t == 0) g_off[N_NODES] = N_EDGES;
}

__global__ void k_scatter(const float* __restrict__ pos,
                          const int* __restrict__ snd, const int* __restrict__ rcv) {
    int e = blockIdx.x * blockDim.x + threadIdx.x;
    if (e >= N_EDGES) return;
    int s = snd[e], r = rcv[e];
    float sx = pos[3*s+0], sy = pos[3*s+1], sz = pos[3*s+2];
    float rx = pos[3*r+0], ry = pos[3*r+1], rz = pos[3*r+2];
    float dx = rx - sx, dy = ry - sy, dz = rz - sz;
    float dist = sqrtf(dx*dx + dy*dy + dz*dz);
    float inv = 1.0f / fmaxf(dist, 1e-9f);
    int slot = atomicAdd(&g_cur[r], 1);
    g_sk[slot]  = make_int2(s, r);
    g_geo[slot] = make_float4(dx * inv, dy * inv, dz * inv, dist);
}

// ---------------- edge kernels (sorted + segmented collapse + RED) -----------

// Layer 1: paths 0,1  (x0 = w_si1 * nf fused)
__global__ void k_edge1(const float* __restrict__ nf, const float* __restrict__ wsi1,
                        const float* __restrict__ rw1, const float* __restrict__ rb1,
                        const float* __restrict__ rw2, const float* __restrict__ rb2) {
    LOAD_RADIAL_SMEM(rw1, rb1, rw2, rb2);
    __shared__ float s1[4];
    if (threadIdx.x < 4) s1[threadIdx.x] = wsi1[threadIdx.x];
    __syncthreads();

    int e = blockIdx.x * blockDim.x + threadIdx.x;   // N_EDGES % 256 == 0
    int2 sk = g_sk[e];
    int s = sk.x, r = sk.y;
    float4 g = g_geo[e];
    SEG_SETUP();

    float rbf[8];
    rbf_from_dist(g.w, rbf);
    float R0[4], R1[4];
    radial(0, rbf, R0, sw1, sb1, sw2, sb2);
    radial(1, rbf, R1, sw1, sb1, sw2, sb2);
    float nfv = __ldg(&nf[s]);
    float xs[4];
#pragma unroll
    for (int c = 0; c < 4; c++) xs[c] = s1[c] * nfv;

    segred4(R0[0]*xs[0], R0[1]*xs[1], R0[2]*xs[2], R0[3]*xs[3], p, head, &g_a0[r*4]);

    float m[12];
#pragma unroll
    for (int c = 0; c < 4; c++) {
        float t = R1[c] * xs[c];
        m[c*3+0] = t*g.x; m[c*3+1] = t*g.y; m[c*3+2] = t*g.z;
    }
    segred4(m[0], m[1], m[2],  m[3],  p, head, &g_a1[r*12+0]);
    segred4(m[4], m[5], m[6],  m[7],  p, head, &g_a1[r*12+4]);
    segred4(m[8], m[9], m[10], m[11], p, head, &g_a1[r*12+8]);
}

// node update 1: si2 + gate
__global__ void k_node1(const float* __restrict__ w20, const float* __restrict__ w21) {
    int n = blockIdx.x * blockDim.x + threadIdx.x;
    if (n >= N_NODES) return;
    float4 a0 = ((const float4*)g_a0)[n];
    float in0[4] = {a0.x, a0.y, a0.z, a0.w};
    float out0[4];
#pragma unroll
    for (int o = 0; o < 4; o++) {
        float sacc = 0.f;
#pragma unroll
        for (int i = 0; i < 4; i++) sacc = fmaf(__ldg(&w20[o*4+i]), in0[i], sacc);
        out0[o] = sacc * sigmoidf(sacc);
    }
    ((float4*)g_x0b)[n] = make_float4(out0[0], out0[1], out0[2], out0[3]);

    float a1[12];
    float4 t0 = ((const float4*)g_a1)[n*3+0];
    float4 t1 = ((const float4*)g_a1)[n*3+1];
    float4 t2 = ((const float4*)g_a1)[n*3+2];
    a1[0]=t0.x; a1[1]=t0.y; a1[2]=t0.z; a1[3]=t0.w;
    a1[4]=t1.x; a1[5]=t1.y; a1[6]=t1.z; a1[7]=t1.w;
    a1[8]=t2.x; a1[9]=t2.y; a1[10]=t2.z; a1[11]=t2.w;
    float out1[12];
#pragma unroll
    for (int o = 0; o < 4; o++) {
        float vx = 0.f, vy = 0.f, vz = 0.f;
#pragma unroll
        for (int i = 0; i < 4; i++) {
            float w = __ldg(&w21[o*4+i]);
            vx = fmaf(w, a1[i*3+0], vx);
            vy = fmaf(w, a1[i*3+1], vy);
            vz = fmaf(w, a1[i*3+2], vz);
        }
        float nrm = sqrtf(vx*vx + vy*vy + vz*vz);
        float gt = sigmoidf(nrm);
        out1[o*3+0] = vx*gt; out1[o*3+1] = vy*gt; out1[o*3+2] = vz*gt;
    }
    ((float4*)g_x1b)[n*3+0] = make_float4(out1[0], out1[1], out1[2],  out1[3]);
    ((float4*)g_x1b)[n*3+1] = make_float4(out1[4], out1[5], out1[6],  out1[7]);
    ((float4*)g_x1b)[n*3+2] = make_float4(out1[8], out1[9], out1[10], out1[11]);
}

// Layer 2: paths 2..6
__global__ void k_edge2(const float* __restrict__ rw1, const float* __restrict__ rb1,
                        const float* __restrict__ rw2, const float* __restrict__ rb2) {
    LOAD_RADIAL_SMEM(rw1, rb1, rw2, rb2);
    int e = blockIdx.x * blockDim.x + threadIdx.x;
    int2 sk = g_sk[e];
    int s = sk.x, r = sk.y;
    float4 g = g_geo[e];
    SEG_SETUP();

    float ux = g.x, uy = g.y, uz = g.z;
    float rbf[8];
    rbf_from_dist(g.w, rbf);

    float4 x0 = ((const float4*)g_x0b)[s];
    float xs[4] = {x0.x, x0.y, x0.z, x0.w};
    float x1[12];
    {
        float4 t0 = ((const float4*)g_x1b)[s*3+0];
        float4 t1 = ((const float4*)g_x1b)[s*3+1];
        float4 t2 = ((const float4*)g_x1b)[s*3+2];
        x1[0]=t0.x; x1[1]=t0.y; x1[2]=t0.z; x1[3]=t0.w;
        x1[4]=t1.x; x1[5]=t1.y; x1[6]=t1.z; x1[7]=t1.w;
        x1[8]=t2.x; x1[9]=t2.y; x1[10]=t2.z; x1[11]=t2.w;
    }

    float R[4];
    // p00_0 : R2 * x0s -> b0[0:4]
    radial(2, rbf, R, sw1, sb1, sw2, sb2);
    segred4(R[0]*xs[0], R[1]*xs[1], R[2]*xs[2], R[3]*xs[3], p, head, &g_b0[r*8]);

    // p11_0 : R5 * (x1s . u)/sqrt3 -> b0[4:8]
    radial(5, rbf, R, sw1, sb1, sw2, sb2);
    {
        float d0 = x1[0]*ux + x1[1]*uy + x1[2]*uz;
        float d1 = x1[3]*ux + x1[4]*uy + x1[5]*uz;
        float d2 = x1[6]*ux + x1[7]*uy + x1[8]*uz;
        float d3 = x1[9]*ux + x1[10]*uy + x1[11]*uz;
        segred4(R[0]*d0*INV_SQRT3, R[1]*d1*INV_SQRT3,
                R[2]*d2*INV_SQRT3, R[3]*d3*INV_SQRT3, p, head, &g_b0[r*8+4]);
    }

    float* b1base = &g_b1[r*36];
    // p01_1 : R3 * x0s * u -> b1[0..11]
    radial(3, rbf, R, sw1, sb1, sw2, sb2);
    {
        float m[12];
#pragma unroll
        for (int c = 0; c < 4; c++) {
            float t = R[c] * xs[c];
            m[c*3+0]=t*ux; m[c*3+1]=t*uy; m[c*3+2]=t*uz;
        }
        segred4(m[0],m[1],m[2], m[3],  p, head, b1base+0);
        segred4(m[4],m[5],m[6], m[7],  p, head, b1base+4);
        segred4(m[8],m[9],m[10],m[11], p, head, b1base+8);
    }
    // p10_1 : R4 * x1s -> b1[12..23]
    radial(4, rbf, R, sw1, sb1, sw2, sb2);
    {
        float m[12];
#pragma unroll
        for (int c = 0; c < 4; c++) {
            m[c*3+0]=R[c]*x1[c*3+0]; m[c*3+1]=R[c]*x1[c*3+1]; m[c*3+2]=R[c]*x1[c*3+2];
        }
        segred4(m[0],m[1],m[2], m[3],  p, head, b1base+12);
        segred4(m[4],m[5],m[6], m[7],  p, head, b1base+16);
        segred4(m[8],m[9],m[10],m[11], p, head, b1base+20);
    }
    // p11_1 : R6 * cross(x1s,u)/sqrt2 -> b1[24..35]
    radial(6, rbf, R, sw1, sb1, sw2, sb2);
    {
        float m[12];
#pragma unroll
        for (int c = 0; c < 4; c++) {
            float ax = x1[c*3+0], ay = x1[c*3+1], az = x1[c*3+2];
            float cx = ay*uz - az*uy;
            float cy = az*ux - ax*uz;
            float cz = ax*uy - ay*ux;
            float t = R[c] * INV_SQRT2;
            m[c*3+0]=t*cx; m[c*3+1]=t*cy; m[c*3+2]=t*cz;
        }
        segred4(m[0],m[1],m[2], m[3],  p, head, b1base+24);
        segred4(m[4],m[5],m[6], m[7],  p, head, b1base+28);
        segred4(m[8],m[9],m[10],m[11], p, head, b1base+32);
    }
}

// node update 2: si3 + gate
__global__ void k_node2(const float* __restrict__ w30, const float* __restrict__ w31) {
    int n = blockIdx.x * blockDim.x + threadIdx.x;
    if (n >= N_NODES) return;
    float b0[8];
    {
        float4 t0 = ((const float4*)g_b0)[n*2+0];
        float4 t1 = ((const float4*)g_b0)[n*2+1];
        b0[0]=t0.x; b0[1]=t0.y; b0[2]=t0.z; b0[3]=t0.w;
        b0[4]=t1.x; b0[5]=t1.y; b0[6]=t1.z; b0[7]=t1.w;
    }
    float out0[4];
#pragma unroll
    for (int o = 0; o < 4; o++) {
        float sacc = 0.f;
#pragma unroll
        for (int i = 0; i < 8; i++) sacc = fmaf(__ldg(&w30[o*8+i]), b0[i], sacc);
        out0[o] = sacc * sigmoidf(sacc);
    }
    ((float4*)g_x0c)[n] = make_float4(out0[0], out0[1], out0[2], out0[3]);

    float b1[36];
#pragma unroll
    for (int q = 0; q < 9; q++) {
        float4 t = ((const float4*)g_b1)[n*9+q];
        b1[q*4+0]=t.x; b1[q*4+1]=t.y; b1[q*4+2]=t.z; b1[q*4+3]=t.w;
    }
    float out1[12];
#pragma unroll
    for (int o = 0; o < 4; o++) {
        float vx = 0.f, vy = 0.f, vz = 0.f;
#pragma unroll
        for (int i = 0; i < 12; i++) {
            float w = __ldg(&w31[o*12+i]);
            vx = fmaf(w, b1[i*3+0], vx);
            vy = fmaf(w, b1[i*3+1], vy);
            vz = fmaf(w, b1[i*3+2], vz);
        }
        float nrm = sqrtf(vx*vx + vy*vy + vz*vz);
        float gt = sigmoidf(nrm);
        out1[o*3+0]=vx*gt; out1[o*3+1]=vy*gt; out1[o*3+2]=vz*gt;
    }
    ((float4*)g_x1c)[n*3+0] = make_float4(out1[0], out1[1], out1[2],  out1[3]);
    ((float4*)g_x1c)[n*3+1] = make_float4(out1[4], out1[5], out1[6],  out1[7]);
    ((float4*)g_x1c)[n*3+2] = make_float4(out1[8], out1[9], out1[10], out1[11]);
}

// Layer 3: paths 7, 8
__global__ void k_edge3(const float* __restrict__ rw1, const float* __restrict__ rb1,
                        const float* __restrict__ rw2, const float* __restrict__ rb2) {
    LOAD_RADIAL_SMEM(rw1, rb1, rw2, rb2);
    int e = blockIdx.x * blockDim.x + threadIdx.x;
    int2 sk = g_sk[e];
    int s = sk.x, r = sk.y;
    float4 g = g_geo[e];
    SEG_SETUP();

    float rbf[8];
    rbf_from_dist(g.w, rbf);
    float R[4];

    float4 x0 = ((const float4*)g_x0c)[s];
    radial(7, rbf, R, sw1, sb1, sw2, sb2);
    segred4(R[0]*x0.x, R[1]*x0.y, R[2]*x0.z, R[3]*x0.w, p, head, &g_c0[r*8]);

    radial(8, rbf, R, sw1, sb1, sw2, sb2);
    float4 t0 = ((const float4*)g_x1c)[s*3+0];
    float4 t1 = ((const float4*)g_x1c)[s*3+1];
    float4 t2 = ((const float4*)g_x1c)[s*3+2];
    float d0 = t0.x*g.x + t0.y*g.y + t0.z*g.z;
    float d1 = t0.w*g.x + t1.x*g.y + t1.y*g.z;
    float d2 = t1.z*g.x + t1.w*g.y + t2.x*g.z;
    float d3 = t2.y*g.x + t2.z*g.y + t2.w*g.z;
    segred4(R[0]*d0*INV_SQRT3, R[1]*d1*INV_SQRT3,
            R[2]*d2*INV_SQRT3, R[3]*d3*INV_SQRT3, p, head, &g_c0[r*8+4]);
}

// readout: per-node si4 + silu, warp-reduce 32 nodes/graph, apply w_out
__global__ void k_final(const float* __restrict__ w4, const float* __restrict__ wout,
                        float* __restrict__ out) {
    int gw = (blockIdx.x * blockDim.x + threadIdx.x) >> 5;
    int lane = threadIdx.x & 31;
    if (gw >= N_GRAPH) return;
    int n = gw * NPG + lane;
    float c0[8];
    {
        float4 t0 = ((const float4*)g_c0)[n*2+0];
        float4 t1 = ((const float4*)g_c0)[n*2+1];
        c0[0]=t0.x; c0[1]=t0.y; c0[2]=t0.z; c0[3]=t0.w;
        c0[4]=t1.x; c0[5]=t1.y; c0[6]=t1.z; c0[7]=t1.w;
    }
    float f[4];
#pragma unroll
    for (int o = 0; o < 4; o++) {
        float sacc = 0.f;
#pragma unroll
        for (int i = 0; i < 8; i++) sacc = fmaf(__ldg(&w4[o*8+i]), c0[i], sacc);
        f[o] = sacc * sigmoidf(sacc);
    }
#pragma unroll
    for (int o = 0; o < 4; o++) {
#pragma unroll
        for (int off = 16; off > 0; off >>= 1)
            f[o] += __shfl_xor_sync(FULLM, f[o], off);
    }
    if (lane < 8) {
        float acc = 0.f;
#pragma unroll
        for (int o = 0; o < 4; o++) acc = fmaf(__ldg(&wout[lane*4+o]), f[o], acc);
        out[gw*8 + lane] = acc;
    }
}

// ---------------- launch ----------------------------------------------------
extern "C" void kernel_launch(void* const* d_in, const int* in_sizes, int n_in,
                              void* d_out, int out_size) {
    const float* pos   = (const float*)d_in[0];
    const float* nf    = (const float*)d_in[1];
    const float* w_si1 = (const float*)d_in[2];
    const float* w20   = (const float*)d_in[3];
    const float* w21   = (const float*)d_in[4];
    const float* w30   = (const float*)d_in[5];
    const float* w31   = (const float*)d_in[6];
    const float* w4    = (const float*)d_in[7];
    const float* wout  = (const float*)d_in[8];
    const float* rw1   = (const float*)d_in[9];
    const float* rb1   = (const float*)d_in[10];
    const float* rw2   = (const float*)d_in[11];
    const float* rb2   = (const float*)d_in[12];
    const int*   snd   = (const int*)d_in[13];
    const int*   rcv   = (const int*)d_in[14];
    float* out = (float*)d_out;

    const int TB = 256;
    k_init   <<<2048, TB>>>();
    k_hist   <<<N_EDGES/TB, TB>>>(rcv);
    k_scanA  <<<256, 256>>>();
    k_scanB  <<<1, 256>>>();
    k_scanC  <<<256, 256>>>();
    k_scatter<<<N_EDGES/TB, TB>>>(pos, snd, rcv);
    k_edge1  <<<N_EDGES/TB, TB>>>(nf, w_si1, rw1, rb1, rw2, rb2);
    k_node1  <<<N_NODES/TB, TB>>>(w20, w21);
    k_edge2  <<<N_EDGES/TB, TB>>>(rw1, rb1, rw2, rb2);
    k_node2  <<<N_NODES/TB, TB>>>(w30, w31);
    k_edge3  <<<N_EDGES/TB, TB>>>(rw1, rb1, rw2, rb2);
    k_final  <<<(N_GRAPH * 32)/TB, TB>>>(w4, wout, out);
}

// round 7
// speedup vs baseline: 3.3620x; 1.0583x over previous
#include <cuda_runtime.h>
#include <cuda_fp16.h>
#include <cstdint>

#define N_GRAPH   4096
#define NPG       32
#define N_NODES   (N_GRAPH * NPG)      // 131072
#define N_EDGES   (N_NODES * 16)       // 2097152
#define INV_SQRT3 0.57735026918962576451f
#define INV_SQRT2 0.70710678118654752440f
#define FULLM     0xFFFFFFFFu

// ---------------- scratch (static device arrays) -----------------------------
__device__ int   g_cnt[N_NODES];
__device__ int   g_off[N_NODES + 1];
__device__ int   g_cur[N_NODES];
__device__ int   g_bs [256];
__device__ __align__(8)  int2   g_sk [N_EDGES];   // {sender, receiver}, receiver-sorted
__device__ __align__(16) float4 g_geo[N_EDGES];   // ux,uy,uz,dist

__device__ __align__(16) float g_a0 [N_NODES * 4];
__device__ __align__(16) float g_a1 [N_NODES * 12];
__device__ __align__(16) __half g_xb[N_NODES * 16];  // packed x0b(4)+x1b(12), fp16
__device__ __align__(16) float g_b0 [N_NODES * 8];
__device__ __align__(16) float g_b1 [N_NODES * 36];
__device__ __align__(16) __half g_xc[N_NODES * 16];  // packed x0c(4)+x1c(12), fp16
__device__ __align__(16) float g_c0 [N_NODES * 8];

// ---------------- helpers ---------------------------------------------------
__device__ __forceinline__ void red4(float* p, float a, float b, float c, float d) {
    asm volatile("red.global.add.v4.f32 [%0], {%1,%2,%3,%4};"
                 :: "l"(p), "f"(a), "f"(b), "f"(c), "f"(d) : "memory");
}

__device__ __forceinline__ float sigmoidf(float x) {
    return 1.0f / (1.0f + __expf(-x));
}

__device__ __forceinline__ void rbf_from_dist(float dist, float rbf[8]) {
#pragma unroll
    for (int b = 0; b < 8; b++) {
        float t = dist - 0.5f * (float)b;          // centers = linspace(0,3.5,8)
        rbf[b] = __expf(-4.0f * t * t);
    }
}

// one radial path: R[4] = relu(rbf @ w1[p] + b1[p]) @ w2[p] + b2[p]
__device__ __forceinline__ void radial(int p, const float rbf[8], float R[4],
                                       const float* sw1, const float* sb1,
                                       const float* sw2, const float* sb2) {
    float h[8];
    const float* w1 = sw1 + p * 64;
#pragma unroll
    for (int j = 0; j < 8; j++) h[j] = sb1[p*8 + j];
#pragma unroll
    for (int b = 0; b < 8; b++) {
        float rb = rbf[b];
#pragma unroll
        for (int j = 0; j < 8; j++) h[j] = fmaf(rb, w1[b*8 + j], h[j]);
    }
#pragma unroll
    for (int j = 0; j < 8; j++) h[j] = fmaxf(h[j], 0.0f);
    const float* w2 = sw2 + p * 32;
#pragma unroll
    for (int c = 0; c < 4; c++) R[c] = sb2[p*4 + c];
#pragma unroll
    for (int j = 0; j < 8; j++) {
        float hj = h[j];
#pragma unroll
        for (int c = 0; c < 4; c++) R[c] = fmaf(hj, w2[j*4 + c], R[c]);
    }
}

// pack 16 floats -> 32B (8 half2) and store as 2 uint4
__device__ __forceinline__ void store_packed16(__half* base, int n, const float* v) {
    uint4 pk[2];
    __half2* hp = reinterpret_cast<__half2*>(pk);
#pragma unroll
    for (int i = 0; i < 8; i++) hp[i] = __floats2half2_rn(v[2*i], v[2*i+1]);
    reinterpret_cast<uint4*>(base)[2*n+0] = pk[0];
    reinterpret_cast<uint4*>(base)[2*n+1] = pk[1];
}

// load 32B packed -> 16 floats
__device__ __forceinline__ void load_packed16(const __half* base, int n, float* v) {
    uint4 pk[2];
    pk[0] = reinterpret_cast<const uint4*>(base)[2*n+0];
    pk[1] = reinterpret_cast<const uint4*>(base)[2*n+1];
    const __half2* hp = reinterpret_cast<const __half2*>(pk);
#pragma unroll
    for (int i = 0; i < 8; i++) {
        float2 f = __half22float2(hp[i]);
        v[2*i] = f.x; v[2*i+1] = f.y;
    }
}

// segmented warp sum of 4 values over contiguous equal-receiver runs.
__device__ __forceinline__ void segred4(float v0, float v1, float v2, float v3,
                                        const bool p[5], bool head, float* addr) {
#pragma unroll
    for (int i = 0, off = 1; i < 5; i++, off <<= 1) {
        float t0 = __shfl_down_sync(FULLM, v0, off);
        float t1 = __shfl_down_sync(FULLM, v1, off);
        float t2 = __shfl_down_sync(FULLM, v2, off);
        float t3 = __shfl_down_sync(FULLM, v3, off);
        if (p[i]) { v0 += t0; v1 += t1; v2 += t2; v3 += t3; }
    }
    if (head) red4(addr, v0, v1, v2, v3);
}

#define SEG_SETUP()                                                            \
    int lane = threadIdx.x & 31;                                               \
    uint32_t seg = __match_any_sync(FULLM, r);                                 \
    bool head = (lane == (__ffs(seg) - 1));                                    \
    bool p[5];                                                                 \
    {                                                                          \
        _Pragma("unroll")                                                      \
        for (int i = 0, off = 1; i < 5; i++, off <<= 1) {                      \
            int ln = lane + off;                                               \
            p[i] = (ln < 32) && ((seg >> ln) & 1u);                            \
        }                                                                      \
    }

#define LOAD_RADIAL_SMEM(rw1, rb1, rw2, rb2)                                   \
    __shared__ float sw1[576], sb1[72], sw2[288], sb2[36];                     \
    for (int i = threadIdx.x; i < 576; i += blockDim.x) sw1[i] = rw1[i];       \
    for (int i = threadIdx.x; i < 72;  i += blockDim.x) sb1[i] = rb1[i];       \
    for (int i = threadIdx.x; i < 288; i += blockDim.x) sw2[i] = rw2[i];       \
    for (int i = threadIdx.x; i < 36;  i += blockDim.x) sb2[i] = rb2[i];       \
    __syncthreads();

// ---------------- init: zero counters + accumulators -------------------------
__global__ void k_init() {
    long i0 = (long)blockIdx.x * blockDim.x + threadIdx.x;
    long stride = (long)gridDim.x * blockDim.x;
    for (long i = i0; i < N_NODES / 4; i += stride)
        ((int4*)g_cnt)[i] = make_int4(0, 0, 0, 0);
    float4 z = make_float4(0.f, 0.f, 0.f, 0.f);
    for (long i = i0; i < N_NODES;     i += stride) ((float4*)g_a0)[i] = z;
    for (long i = i0; i < N_NODES * 3; i += stride) ((float4*)g_a1)[i] = z;
    for (long i = i0; i < N_NODES * 2; i += stride) ((float4*)g_b0)[i] = z;
    for (long i = i0; i < N_NODES * 9; i += stride) ((float4*)g_b1)[i] = z;
    for (long i = i0; i < N_NODES * 2; i += stride) ((float4*)g_c0)[i] = z;
}

// ---------------- CSR build --------------------------------------------------
__global__ void k_hist(const int* __restrict__ rcv) {
    int e = blockIdx.x * blockDim.x + threadIdx.x;
    if (e < N_EDGES) atomicAdd(&g_cnt[rcv[e]], 1);
}

__global__ void k_scanA() {
    __shared__ int sd[256];
    int b = blockIdx.x, t = threadIdx.x;
    int i = b * 512 + t * 2;
    int e0 = g_cnt[i], e1 = g_cnt[i + 1];
    int s = e0 + e1;
    sd[t] = s;
    __syncthreads();
#pragma unroll
    for (int off = 1; off < 256; off <<= 1) {
        int v = (t >= off) ? sd[t - off] : 0;
        __syncthreads();
        sd[t] += v;
        __syncthreads();
    }
    int incl = sd[t];
    int excl = incl - s;
    g_off[i]     = excl;
    g_off[i + 1] = excl + e0;
    if (t == 255) g_bs[b] = incl;
}

__global__ void k_scanB() {
    __shared__ int sd[256];
    int t = threadIdx.x;
    int v = g_bs[t];
    sd[t] = v;
    __syncthreads();
#pragma unroll
    for (int off = 1; off < 256; off <<= 1) {
        int x = (t >= off) ? sd[t - off] : 0;
        __syncthreads();
        sd[t] += x;
        __syncthreads();
    }
    g_bs[t] = sd[t] - v;   // exclusive
}

__global__ void k_scanC() {
    int b = blockIdx.x, t = threadIdx.x;
    int add = g_bs[b];
    int i = b * 512 + t * 2;
    int o0 = g_off[i] + add, o1 = g_off[i + 1] + add;
    g_off[i] = o0;  g_off[i + 1] = o1;
    g_cur[i] = o0;  g_cur[i + 1] = o1;
    if (b == 0 && t == 0) g_off[N_NODES] = N_EDGES;
}

__global__ void k_scatter(const float* __restrict__ pos,
                          const int* __restrict__ snd, const int* __restrict__ rcv) {
    int e = blockIdx.x * blockDim.x + threadIdx.x;
    if (e >= N_EDGES) return;
    int s = snd[e], r = rcv[e];
    float sx = pos[3*s+0], sy = pos[3*s+1], sz = pos[3*s+2];
    float rx = pos[3*r+0], ry = pos[3*r+1], rz = pos[3*r+2];
    float dx = rx - sx, dy = ry - sy, dz = rz - sz;
    float dist = sqrtf(dx*dx + dy*dy + dz*dz);
    float inv = 1.0f / fmaxf(dist, 1e-9f);
    int slot = atomicAdd(&g_cur[r], 1);
    g_sk[slot]  = make_int2(s, r);
    g_geo[slot] = make_float4(dx * inv, dy * inv, dz * inv, dist);
}

// ---------------- edge kernels (sorted + segmented collapse + RED) -----------

// Layer 1: paths 0,1
__global__ void k_edge1(const float* __restrict__ nf, const float* __restrict__ wsi1,
                        const float* __restrict__ rw1, const float* __restrict__ rb1,
                        const float* __restrict__ rw2, const float* __restrict__ rb2) {
    LOAD_RADIAL_SMEM(rw1, rb1, rw2, rb2);
    __shared__ float s1[4];
    if (threadIdx.x < 4) s1[threadIdx.x] = wsi1[threadIdx.x];
    __syncthreads();

    int e = blockIdx.x * blockDim.x + threadIdx.x;
    int2 sk = g_sk[e];
    int s = sk.x, r = sk.y;
    float4 g = g_geo[e];
    SEG_SETUP();

    float rbf[8];
    rbf_from_dist(g.w, rbf);
    float R0[4], R1[4];
    radial(0, rbf, R0, sw1, sb1, sw2, sb2);
    radial(1, rbf, R1, sw1, sb1, sw2, sb2);
    float nfv = __ldg(&nf[s]);
    float xs[4];
#pragma unroll
    for (int c = 0; c < 4; c++) xs[c] = s1[c] * nfv;

    segred4(R0[0]*xs[0], R0[1]*xs[1], R0[2]*xs[2], R0[3]*xs[3], p, head, &g_a0[r*4]);

    float m[12];
#pragma unroll
    for (int c = 0; c < 4; c++) {
        float t = R1[c] * xs[c];
        m[c*3+0] = t*g.x; m[c*3+1] = t*g.y; m[c*3+2] = t*g.z;
    }
    segred4(m[0], m[1], m[2],  m[3],  p, head, &g_a1[r*12+0]);
    segred4(m[4], m[5], m[6],  m[7],  p, head, &g_a1[r*12+4]);
    segred4(m[8], m[9], m[10], m[11], p, head, &g_a1[r*12+8]);
}

// node update 1: si2 + gate -> packed fp16
__global__ void k_node1(const float* __restrict__ w20, const float* __restrict__ w21) {
    int n = blockIdx.x * blockDim.x + threadIdx.x;
    if (n >= N_NODES) return;
    float4 a0 = ((const float4*)g_a0)[n];
    float in0[4] = {a0.x, a0.y, a0.z, a0.w};
    float outv[16];
#pragma unroll
    for (int o = 0; o < 4; o++) {
        float sacc = 0.f;
#pragma unroll
        for (int i = 0; i < 4; i++) sacc = fmaf(__ldg(&w20[o*4+i]), in0[i], sacc);
        outv[o] = sacc * sigmoidf(sacc);
    }

    float a1[12];
    float4 t0 = ((const float4*)g_a1)[n*3+0];
    float4 t1 = ((const float4*)g_a1)[n*3+1];
    float4 t2 = ((const float4*)g_a1)[n*3+2];
    a1[0]=t0.x; a1[1]=t0.y; a1[2]=t0.z; a1[3]=t0.w;
    a1[4]=t1.x; a1[5]=t1.y; a1[6]=t1.z; a1[7]=t1.w;
    a1[8]=t2.x; a1[9]=t2.y; a1[10]=t2.z; a1[11]=t2.w;
#pragma unroll
    for (int o = 0; o < 4; o++) {
        float vx = 0.f, vy = 0.f, vz = 0.f;
#pragma unroll
        for (int i = 0; i < 4; i++) {
            float w = __ldg(&w21[o*4+i]);
            vx = fmaf(w, a1[i*3+0], vx);
            vy = fmaf(w, a1[i*3+1], vy);
            vz = fmaf(w, a1[i*3+2], vz);
        }
        float nrm = sqrtf(vx*vx + vy*vy + vz*vz);
        float gt = sigmoidf(nrm);
        outv[4+o*3+0] = vx*gt; outv[4+o*3+1] = vy*gt; outv[4+o*3+2] = vz*gt;
    }
    store_packed16(g_xb, n, outv);
}

// Layer 2: paths 2..6
__global__ void k_edge2(const float* __restrict__ rw1, const float* __restrict__ rb1,
                        const float* __restrict__ rw2, const float* __restrict__ rb2) {
    LOAD_RADIAL_SMEM(rw1, rb1, rw2, rb2);
    int e = blockIdx.x * blockDim.x + threadIdx.x;
    int2 sk = g_sk[e];
    int s = sk.x, r = sk.y;
    float4 g = g_geo[e];
    SEG_SETUP();

    float ux = g.x, uy = g.y, uz = g.z;
    float rbf[8];
    rbf_from_dist(g.w, rbf);

    float v[16];
    load_packed16(g_xb, s, v);
    float* xs = v;        // v[0..3]
    float* x1 = v + 4;    // v[4..15]

    float R[4];
    // p00_0 : R2 * x0s -> b0[0:4]
    radial(2, rbf, R, sw1, sb1, sw2, sb2);
    segred4(R[0]*xs[0], R[1]*xs[1], R[2]*xs[2], R[3]*xs[3], p, head, &g_b0[r*8]);

    // p11_0 : R5 * (x1s . u)/sqrt3 -> b0[4:8]
    radial(5, rbf, R, sw1, sb1, sw2, sb2);
    {
        float d0 = x1[0]*ux + x1[1]*uy + x1[2]*uz;
        float d1 = x1[3]*ux + x1[4]*uy + x1[5]*uz;
        float d2 = x1[6]*ux + x1[7]*uy + x1[8]*uz;
        float d3 = x1[9]*ux + x1[10]*uy + x1[11]*uz;
        segred4(R[0]*d0*INV_SQRT3, R[1]*d1*INV_SQRT3,
                R[2]*d2*INV_SQRT3, R[3]*d3*INV_SQRT3, p, head, &g_b0[r*8+4]);
    }

    float* b1base = &g_b1[r*36];
    // p01_1 : R3 * x0s * u -> b1[0..11]
    radial(3, rbf, R, sw1, sb1, sw2, sb2);
    {
        float m[12];
#pragma unroll
        for (int c = 0; c < 4; c++) {
            float t = R[c] * xs[c];
            m[c*3+0]=t*ux; m[c*3+1]=t*uy; m[c*3+2]=t*uz;
        }
        segred4(m[0],m[1],m[2], m[3],  p, head, b1base+0);
        segred4(m[4],m[5],m[6], m[7],  p, head, b1base+4);
        segred4(m[8],m[9],m[10],m[11], p, head, b1base+8);
    }
    // p10_1 : R4 * x1s -> b1[12..23]
    radial(4, rbf, R, sw1, sb1, sw2, sb2);
    {
        float m[12];
#pragma unroll
        for (int c = 0; c < 4; c++) {
            m[c*3+0]=R[c]*x1[c*3+0]; m[c*3+1]=R[c]*x1[c*3+1]; m[c*3+2]=R[c]*x1[c*3+2];
        }
        segred4(m[0],m[1],m[2], m[3],  p, head, b1base+12);
        segred4(m[4],m[5],m[6], m[7],  p, head, b1base+16);
        segred4(m[8],m[9],m[10],m[11], p, head, b1base+20);
    }
    // p11_1 : R6 * cross(x1s,u)/sqrt2 -> b1[24..35]
    radial(6, rbf, R, sw1, sb1, sw2, sb2);
    {
        float m[12];
#pragma unroll
        for (int c = 0; c < 4; c++) {
            float ax = x1[c*3+0], ay = x1[c*3+1], az = x1[c*3+2];
            float cx = ay*uz - az*uy;
            float cy = az*ux - ax*uz;
            float cz = ax*uy - ay*ux;
            float t = R[c] * INV_SQRT2;
            m[c*3+0]=t*cx; m[c*3+1]=t*cy; m[c*3+2]=t*cz;
        }
        segred4(m[0],m[1],m[2], m[3],  p, head, b1base+24);
        segred4(m[4],m[5],m[6], m[7],  p, head, b1base+28);
        segred4(m[8],m[9],m[10],m[11], p, head, b1base+32);
    }
}

// node update 2: si3 + gate -> packed fp16
__global__ void k_node2(const float* __restrict__ w30, const float* __restrict__ w31) {
    int n = blockIdx.x * blockDim.x + threadIdx.x;
    if (n >= N_NODES) return;
    float b0[8];
    {
        float4 t0 = ((const float4*)g_b0)[n*2+0];
        float4 t1 = ((const float4*)g_b0)[n*2+1];
        b0[0]=t0.x; b0[1]=t0.y; b0[2]=t0.z; b0[3]=t0.w;
        b0[4]=t1.x; b0[5]=t1.y; b0[6]=t1.z; b0[7]=t1.w;
    }
    float outv[16];
#pragma unroll
    for (int o = 0; o < 4; o++) {
        float sacc = 0.f;
#pragma unroll
        for (int i = 0; i < 8; i++) sacc = fmaf(__ldg(&w30[o*8+i]), b0[i], sacc);
        outv[o] = sacc * sigmoidf(sacc);
    }

    float b1[36];
#pragma unroll
    for (int q = 0; q < 9; q++) {
        float4 t = ((const float4*)g_b1)[n*9+q];
        b1[q*4+0]=t.x; b1[q*4+1]=t.y; b1[q*4+2]=t.z; b1[q*4+3]=t.w;
    }
#pragma unroll
    for (int o = 0; o < 4; o++) {
        float vx = 0.f, vy = 0.f, vz = 0.f;
#pragma unroll
        for (int i = 0; i < 12; i++) {
            float w = __ldg(&w31[o*12+i]);
            vx = fmaf(w, b1[i*3+0], vx);
            vy = fmaf(w, b1[i*3+1], vy);
            vz = fmaf(w, b1[i*3+2], vz);
        }
        float nrm = sqrtf(vx*vx + vy*vy + vz*vz);
        float gt = sigmoidf(nrm);
        outv[4+o*3+0]=vx*gt; outv[4+o*3+1]=vy*gt; outv[4+o*3+2]=vz*gt;
    }
    store_packed16(g_xc, n, outv);
}

// Layer 3: paths 7, 8
__global__ void k_edge3(const float* __restrict__ rw1, const float* __restrict__ rb1,
                        const float* __restrict__ rw2, const float* __restrict__ rb2) {
    LOAD_RADIAL_SMEM(rw1, rb1, rw2, rb2);
    int e = blockIdx.x * blockDim.x + threadIdx.x;
    int2 sk = g_sk[e];
    int s = sk.x, r = sk.y;
    float4 g = g_geo[e];
    SEG_SETUP();

    float rbf[8];
    rbf_from_dist(g.w, rbf);
    float R[4];

    float v[16];
    load_packed16(g_xc, s, v);

    radial(7, rbf, R, sw1, sb1, sw2, sb2);
    segred4(R[0]*v[0], R[1]*v[1], R[2]*v[2], R[3]*v[3], p, head, &g_c0[r*8]);

    radial(8, rbf, R, sw1, sb1, sw2, sb2);
    const float* x1 = v + 4;
    float d0 = x1[0]*g.x + x1[1]*g.y + x1[2]*g.z;
    float d1 = x1[3]*g.x + x1[4]*g.y + x1[5]*g.z;
    float d2 = x1[6]*g.x + x1[7]*g.y + x1[8]*g.z;
    float d3 = x1[9]*g.x + x1[10]*g.y + x1[11]*g.z;
    segred4(R[0]*d0*INV_SQRT3, R[1]*d1*INV_SQRT3,
            R[2]*d2*INV_SQRT3, R[3]*d3*INV_SQRT3, p, head, &g_c0[r*8+4]);
}

// readout
__global__ void k_final(const float* __restrict__ w4, const float* __restrict__ wout,
                        float* __restrict__ out) {
    int gw = (blockIdx.x * blockDim.x + threadIdx.x) >> 5;
    int lane = threadIdx.x & 31;
    if (gw >= N_GRAPH) return;
    int n = gw * NPG + lane;
    float c0[8];
    {
        float4 t0 = ((const float4*)g_c0)[n*2+0];
        float4 t1 = ((const float4*)g_c0)[n*2+1];
        c0[0]=t0.x; c0[1]=t0.y; c0[2]=t0.z; c0[3]=t0.w;
        c0[4]=t1.x; c0[5]=t1.y; c0[6]=t1.z; c0[7]=t1.w;
    }
    float f[4];
#pragma unroll
    for (int o = 0; o < 4; o++) {
        float sacc = 0.f;
#pragma unroll
        for (int i = 0; i < 8; i++) sacc = fmaf(__ldg(&w4[o*8+i]), c0[i], sacc);
        f[o] = sacc * sigmoidf(sacc);
    }
#pragma unroll
    for (int o = 0; o < 4; o++) {
#pragma unroll
        for (int off = 16; off > 0; off >>= 1)
            f[o] += __shfl_xor_sync(FULLM, f[o], off);
    }
    if (lane < 8) {
        float acc = 0.f;
#pragma unroll
        for (int o = 0; o < 4; o++) acc = fmaf(__ldg(&wout[lane*4+o]), f[o], acc);
        out[gw*8 + lane] = acc;
    }
}

// ---------------- launch ----------------------------------------------------
extern "C" void kernel_launch(void* const* d_in, const int* in_sizes, int n_in,
                              void* d_out, int out_size) {
    const float* pos   = (const float*)d_in[0];
    const float* nf    = (const float*)d_in[1];
    const float* w_si1 = (const float*)d_in[2];
    const float* w20   = (const float*)d_in[3];
    const float* w21   = (const float*)d_in[4];
    const float* w30   = (const float*)d_in[5];
    const float* w31   = (const float*)d_in[6];
    const float* w4    = (const float*)d_in[7];
    const float* wout  = (const float*)d_in[8];
    const float* rw1   = (const float*)d_in[9];
    const float* rb1   = (const float*)d_in[10];
    const float* rw2   = (const float*)d_in[11];
    const float* rb2   = (const float*)d_in[12];
    const int*   snd   = (const int*)d_in[13];
    const int*   rcv   = (const int*)d_in[14];
    float* out = (float*)d_out;

    const int TB = 256;
    k_init   <<<2048, TB>>>();
    k_hist   <<<N_EDGES/TB, TB>>>(rcv);
    k_scanA  <<<256, 256>>>();
    k_scanB  <<<1, 256>>>();
    k_scanC  <<<256, 256>>>();
    k_scatter<<<N_EDGES/TB, TB>>>(pos, snd, rcv);
    k_edge1  <<<N_EDGES/TB, TB>>>(nf, w_si1, rw1, rb1, rw2, rb2);
    k_node1  <<<N_NODES/TB, TB>>>(w20, w21);
    k_edge2  <<<N_EDGES/TB, TB>>>(rw1, rb1, rw2, rb2);
    k_node2  <<<N_NODES/TB, TB>>>(w30, w31);
    k_edge3  <<<N_EDGES/TB, TB>>>(rw1, rb1, rw2, rb2);
    k_final  <<<(N_GRAPH * 32)/TB, TB>>>(w4, wout, out);
}